// round 17
// baseline (speedup 1.0000x reference)
#include <cuda_runtime.h>
#include <cstdint>
#include <math.h>

// CTC forward loss, linear domain, one warp per batch element, per-lane
// power-of-two scaling. Lane l owns s=8l..8l+7 (+shadow s=8l+8 in a256).
// R16: direct-LDG register pipeline (R15) + branch-free renorm performed
// every 8 steps (two 4-step blocks) with two-hop exponent adoption.
// Frontier argument: nonzero lanes form a prefix [0..F]; mass advances
// <=2 positions/step => <=2 lanes per 8-step period, so two shfl-adoption
// hops keep every mass-receiving lane's exponent fresh.

constexpr int N_ = 512;
constexpr int C_ = 80;
constexpr int S_ = 128;
constexpr int T_ = 512;
constexpr int NC = N_ * C_;
constexpr int WPB = 4;

__global__ __launch_bounds__(WPB * 32)
void ctc_kernel(const float* __restrict__ lp, const int* __restrict__ tgt,
                const int* __restrict__ ilen, const int* __restrict__ tlen,
                float* __restrict__ out)
{
    __shared__ float aval[WPB][260];
    __shared__ int   epos[WPB][32];

    const int lane = threadIdx.x & 31;
    const int w    = threadIdx.x >> 5;
    const int n    = blockIdx.x * WPB + w;
    const int len  = ilen[n];            // [T/2, T]
    const int tl   = tlen[n];            // [S/2, S]
    const int hi   = 2 * tl;             // readout states hi, hi-1

    const int4 lab4 = *reinterpret_cast<const int4*>(tgt + n * S_ + 4 * lane);
    const int l0 = lab4.x, l1 = lab4.y, l2 = lab4.z, l3 = lab4.w;
    const int prevlab = __shfl_up_sync(0xffffffffu, l3, 1);
    const float sk0 = (lane > 0 && l0 != prevlab) ? 1.f : 0.f;
    const float sk1 = (l1 != l0) ? 1.f : 0.f;
    const float sk2 = (l2 != l1) ? 1.f : 0.f;
    const float sk3 = (l3 != l2) ? 1.f : 0.f;

    const float* rp = lp + (size_t)n * C_;
    const float* q0 = rp;
    const float* q1 = rp + l0;
    const float* q2 = rp + l1;
    const float* q3 = rp + l2;
    const float* q4 = rp + l3;

    float buf[4][20];
    float egb[4], eg0[4], eg1[4], eg2[4], eg3[4];

    float a0 = 0, a1 = 0, a2 = 0, a3 = 0, a4 = 0, a5 = 0, a6 = 0, a7 = 0, a256 = 0;
    if (lane == 0) { a0 = __expf(__ldg(rp)); a1 = __expf(__ldg(rp + l0)); }

    // Prologue: row-sets for blocks 0,1,2 (rows 1..12) into buf[0..2].
    #pragma unroll
    for (int b = 0; b < 3; ++b)
        #pragma unroll
        for (int j = 0; j < 4; ++j) {
            const int r = 4 * b + 1 + j;
            buf[b][5*j+0] = __ldg(q0 + r * NC);
            buf[b][5*j+1] = __ldg(q1 + r * NC);
            buf[b][5*j+2] = __ldg(q2 + r * NC);
            buf[b][5*j+3] = __ldg(q3 + r * NC);
            buf[b][5*j+4] = __ldg(q4 + r * NC);
        }
    #pragma unroll
    for (int j = 0; j < 4; ++j) {
        egb[j] = __expf(buf[0][5*j+0]);
        eg0[j] = __expf(buf[0][5*j+1]);
        eg1[j] = __expf(buf[0][5*j+2]);
        eg2[j] = __expf(buf[0][5*j+3]);
        eg3[j] = __expf(buf[0][5*j+4]);
    }
    q0 += 13 * NC; q1 += 13 * NC; q2 += 13 * NC; q3 += 13 * NC; q4 += 13 * NC;

    int   E  = 0;
    float sF = (lane == 0) ? 0.f : 1.f;  // 2^(E_prev - E); 0 on lane 0
    const int ibase = lane << 3;

    #define ASTEP(j)                                                        \
    {                                                                       \
        const float pa7 = __shfl_up_sync(0xffffffffu, a7, 1) * sF;          \
        const float n0 = (a0 + pa7) * egb[j];                               \
        const float n1 = (a1 + a0 + sk0 * pa7) * eg0[j];                    \
        const float n2 = (a2 + a1) * egb[j];                                \
        const float n3 = (a3 + a2 + sk1 * a1) * eg1[j];                     \
        const float n4 = (a4 + a3) * egb[j];                                \
        const float n5 = (a5 + a4 + sk2 * a3) * eg2[j];                     \
        const float n6 = (a6 + a5) * egb[j];                                \
        const float n7 = (a7 + a6 + sk3 * a5) * eg3[j];                     \
        a256 = (a256 + a7) * egb[j];                                        \
        a0 = n0; a1 = n1; a2 = n2; a3 = n3;                                 \
        a4 = n4; a5 = n5; a6 = n6; a7 = n7;                                 \
    }

    // Branch-free renorm + two-hop exponent adoption (every 8 steps).
    #define RENORM                                                          \
    {                                                                       \
        float m = fmaxf(fmaxf(fmaxf(a0, a1), fmaxf(a2, a3)),                \
                        fmaxf(fmaxf(a4, a5), fmaxf(a6, a7)));               \
        m = fmaxf(m, a256);                                                 \
        const bool nz = (m > 0.f);                                          \
        int eb = (__float_as_int(m) >> 23) - 127;                           \
        eb = nz ? eb : 0;                                                   \
        const float sc = __int_as_float((127 - eb) << 23);  /* 2^-eb */     \
        E += eb;                                                            \
        a0 *= sc; a1 *= sc; a2 *= sc; a3 *= sc;                             \
        a4 *= sc; a5 *= sc; a6 *= sc; a7 *= sc; a256 *= sc;                 \
        const int E1h = __shfl_up_sync(0xffffffffu, E, 1);                  \
        E = nz ? E : E1h;                                                   \
        const int E2h = __shfl_up_sync(0xffffffffu, E, 1);                  \
        E = nz ? E : E2h;                                                   \
        int dE = E2h - E; dE = max(-126, min(126, dE));                     \
        sF = (lane == 0) ? 0.f : __int_as_float((127 + dE) << 23);          \
    }

    // Block body (no renorm): 4 ASTEPs for block KB; LDG row-set for block
    // KB+3 into buf[(P+3)&3]; exp egs for block KB+1 from buf[(P+1)&3].
    #define BODY(P, GUARD, KB)                                              \
    {                                                                       \
        if (GUARD) {                                                        \
            const int tt = 4 * (KB) + 1;                                    \
            if (tt + 0 < len) ASTEP(0)                                      \
            if (tt + 1 < len) ASTEP(1)                                      \
            if (tt + 2 < len) ASTEP(2)                                      \
            if (tt + 3 < len) ASTEP(3)                                      \
        } else { ASTEP(0) ASTEP(1) ASTEP(2) ASTEP(3) }                      \
        {                                                                   \
            const int r0 = 4 * (KB) + 13;                                   \
            _Pragma("unroll")                                               \
            for (int j = 0; j < 4; ++j) if (r0 + j < T_) {                  \
                buf[((P)+3)&3][5*j+0] = __ldg(q0 + j * NC);                 \
                buf[((P)+3)&3][5*j+1] = __ldg(q1 + j * NC);                 \
                buf[((P)+3)&3][5*j+2] = __ldg(q2 + j * NC);                 \
                buf[((P)+3)&3][5*j+3] = __ldg(q3 + j * NC);                 \
                buf[((P)+3)&3][5*j+4] = __ldg(q4 + j * NC);                 \
            }                                                               \
            q0 += 4 * NC; q1 += 4 * NC; q2 += 4 * NC;                       \
            q3 += 4 * NC; q4 += 4 * NC;                                     \
        }                                                                   \
        _Pragma("unroll")                                                   \
        for (int j = 0; j < 4; ++j) {                                       \
            egb[j] = __expf(buf[((P)+1)&3][5*j+0]);                         \
            eg0[j] = __expf(buf[((P)+1)&3][5*j+1]);                         \
            eg1[j] = __expf(buf[((P)+1)&3][5*j+2]);                         \
            eg2[j] = __expf(buf[((P)+1)&3][5*j+3]);                         \
            eg3[j] = __expf(buf[((P)+1)&3][5*j+4]);                         \
        }                                                                   \
    }

    const int NBfull = (len - 1) >> 2;   // number of complete 4-step blocks
    int kb = 0;
    for (; kb + 4 <= NBfull; kb += 4) {
        BODY(0, false, kb)
        BODY(1, false, kb + 1)
        RENORM
        BODY(2, false, kb + 2)
        BODY(3, false, kb + 3)
        RENORM
    }
    // Guarded tail: blocks kb..kb+3 cover all remaining steps; renorm past
    // len is representation-preserving, so only ASTEPs carry guards.
    BODY(0, true, kb)
    BODY(1, true, kb + 1)
    RENORM
    BODY(2, true, kb + 2)
    BODY(3, true, kb + 3)
    RENORM

    #undef BODY
    #undef RENORM
    #undef ASTEP

    // Readout: alpha_true[s] = aval[s] * 2^E(lane(s)).
    aval[w][ibase + 0] = a0; aval[w][ibase + 1] = a1;
    aval[w][ibase + 2] = a2; aval[w][ibase + 3] = a3;
    aval[w][ibase + 4] = a4; aval[w][ibase + 5] = a5;
    aval[w][ibase + 6] = a6; aval[w][ibase + 7] = a7;
    epos[w][lane] = E;
    if (lane == 31) aval[w][256] = a256;
    __syncwarp();
    if (lane == 0) {
        const float v1 = aval[w][hi];
        const float v2 = aval[w][hi - 1];
        int E1 = epos[w][min(hi >> 3, 31)];
        int E2 = epos[w][(hi - 1) >> 3];
        E1 = (v1 > 0.f) ? E1 : -2000000;
        E2 = (v2 > 0.f) ? E2 : -2000000;
        const int Em = max(E1, E2);
        const double sum = ldexp((double)v1, max(E1 - Em, -1000))
                         + ldexp((double)v2, max(E2 - Em, -1000));
        const double loss = -((double)Em * 0.6931471805599453 + log(sum));
        float lf = (float)loss;
        if (!isfinite(lf) || !(lf < 1e10f)) lf = 0.f;   // zero_infinity
        out[n] = lf;
    }
}

extern "C" void kernel_launch(void* const* d_in, const int* in_sizes, int n_in,
                              void* d_out, int out_size)
{
    const float* lp   = (const float*)d_in[0];
    const int*   tgt  = (const int*)  d_in[1];
    const int*   ilen = (const int*)  d_in[2];
    const int*   tlen = (const int*)  d_in[3];
    float*       out  = (float*)      d_out;

    ctc_kernel<<<N_ / WPB, WPB * 32>>>(lp, tgt, ilen, tlen, out);
}